// round 6
// baseline (speedup 1.0000x reference)
#include <cuda_runtime.h>
#include <cstdint>
#include <cstddef>

// ---------------------------------------------------------------------------
// SO3Reparameterize: z = expmap(x@Wmu+bmu) @ expmap(L @ (sqrt(softplus(x@Wd+bd))*eps))
// Fused skinny GEMM (X[65536,1024] @ W9[1024,9]) + per-row epilogue.
// R6: W persistent in REGISTERS (36/lane, loaded once) -> zero W smem traffic.
//     Block-level split-K: warp w owns k-slice w*128, lane owns 4 k.
//     Per 4-row tile: f32x2 partials -> lane reduction (padded smem) ->
//     cross-warp reduction (parity buffer, 1 barrier/tile). Prefetch next
//     tile's x before the reduction. Deferred epilogue (no reg overlap).
// ---------------------------------------------------------------------------

#define K_DIM     1024
#define THREADS   256
#define WARPS     8
#define TILE_R    4                         // rows per tile
#define NT        8                         // tiles per block
#define ROWS_BLK  (TILE_R * NT)             // 32
#define REDW_STRIDE 37                      // padded lane stride (floats)
#define WPACK_ELEMS ((K_DIM / 4) * 36)      // 9216 floats = 36 KB

__device__ float g_wpack[WPACK_ELEMS];

// Pack Wmu|Wd|Wl ([1024,3] each) into wpack[kb][j][4]: k-group kb (4 k),
// column j in 0..8, 4 k-values contiguous (8B halves are f32x2 pairs).
__global__ void pack_w_kernel(const float* __restrict__ Wmu,
                              const float* __restrict__ Wd,
                              const float* __restrict__ Wl) {
    int idx = blockIdx.x * blockDim.x + threadIdx.x;
    if (idx >= WPACK_ELEMS) return;
    int kb  = idx / 36;
    int rem = idx - kb * 36;
    int j   = rem >> 2;
    int kk  = rem & 3;
    int k   = kb * 4 + kk;
    float v;
    if (j < 3)      v = Wmu[k * 3 + j];
    else if (j < 6) v = Wd [k * 3 + (j - 3)];
    else            v = Wl [k * 3 + (j - 6)];
    g_wpack[idx] = v;
}

// ---- packed f32x2 helpers (sm_100+) ----------------------------------------
__device__ __forceinline__ unsigned long long mul2(unsigned long long a,
                                                   unsigned long long b) {
    unsigned long long r;
    asm("mul.rn.f32x2 %0, %1, %2;" : "=l"(r) : "l"(a), "l"(b));
    return r;
}
__device__ __forceinline__ unsigned long long fma2(unsigned long long a,
                                                   unsigned long long b,
                                                   unsigned long long c) {
    unsigned long long r;
    asm("fma.rn.f32x2 %0, %1, %2, %3;" : "=l"(r) : "l"(a), "l"(b), "l"(c));
    return r;
}
__device__ __forceinline__ float collapse2(unsigned long long v) {
    float lo, hi;
    asm("mov.b64 {%0, %1}, %2;" : "=f"(lo), "=f"(hi) : "l"(v));
    return lo + hi;
}

// ---- epilogue math ---------------------------------------------------------
__device__ __forceinline__ float softplus_f(float z) {
    return fmaxf(z, 0.0f) + log1pf(expf(-fabsf(z)));
}

__device__ __forceinline__ void rodrigues(float vx, float vy, float vz, float R[9]) {
    float th  = sqrtf(vx * vx + vy * vy + vz * vz);
    float inv = 1.0f / th;                 // reference also divides (NaN if 0)
    float kx = vx * inv, ky = vy * inv, kz = vz * inv;
    float s, c;
    sincosf(th, &s, &c);
    float ct = 1.0f - c;
    R[0] = c + ct * kx * kx;  R[1] = ct * kx * ky - s * kz;  R[2] = ct * kx * kz + s * ky;
    R[3] = ct * kx * ky + s * kz;  R[4] = c + ct * ky * ky;  R[5] = ct * ky * kz - s * kx;
    R[6] = ct * kx * kz - s * ky;  R[7] = ct * ky * kz + s * kx;  R[8] = c + ct * kz * kz;
}

__device__ __forceinline__ void row_epilogue(
    const float a[9], const float* __restrict__ eps, float* __restrict__ out,
    int grow, int B, int n,
    const float* __restrict__ bmu,
    const float* __restrict__ bd,
    const float* __restrict__ bl)
{
    float mu0 = a[0] + bmu[0], mu1 = a[1] + bmu[1], mu2 = a[2] + bmu[2];
    float s0 = sqrtf(softplus_f(a[3] + bd[0]));
    float s1 = sqrtf(softplus_f(a[4] + bd[1]));
    float s2 = sqrtf(softplus_f(a[5] + bd[2]));
    float L0 = a[6] + bl[0], L1 = a[7] + bl[1], L2 = a[8] + bl[2];

    float Rm[9];
    rodrigues(mu0, mu1, mu2, Rm);

    for (int ni = 0; ni < n; ni++) {
        const float* e = eps + ((size_t)ni * B + grow) * 3;
        float t0 = s0 * e[0], t1 = s1 * e[1], t2 = s2 * e[2];
        float v0 = t0;
        float v1 = L0 * t0 + t1;
        float v2 = L1 * t0 + L2 * t1 + t2;
        float Rv[9];
        rodrigues(v0, v1, v2, Rv);
        float* o = out + ((size_t)ni * B + grow) * 9;
#pragma unroll
        for (int i = 0; i < 3; i++) {
#pragma unroll
            for (int j = 0; j < 3; j++) {
                o[i * 3 + j] = Rm[i * 3 + 0] * Rv[0 * 3 + j]
                             + Rm[i * 3 + 1] * Rv[1 * 3 + j]
                             + Rm[i * 3 + 2] * Rv[2 * 3 + j];
            }
        }
    }
}

// ---- main fused kernel -----------------------------------------------------
__global__ __launch_bounds__(THREADS, 3)
void so3_kernel(const float* __restrict__ x,
                const float* __restrict__ eps,
                const float* __restrict__ bmu,
                const float* __restrict__ bd,
                const float* __restrict__ bl,
                float* __restrict__ out,
                int B, int n)
{
    __shared__ float redw[WARPS][32 * REDW_STRIDE];  // 37.9 KB lane-reduction
    __shared__ float redbuf2[2][WARPS][36];          // 2.3 KB cross-warp (parity)
    __shared__ float sumbuf[ROWS_BLK * 9];           // 1.2 KB final sums

    const int tid  = threadIdx.x;
    const int warp = tid >> 5;
    const int lane = tid & 31;

    // ---- persistent W: lane's k-group kb = warp*32 + lane (k = kb*4) -------
    ulonglong2 W2[9];
    {
        const ulonglong2* wg = reinterpret_cast<const ulonglong2*>(
            g_wpack + (size_t)(warp * 32 + lane) * 36);
#pragma unroll
        for (int j = 0; j < 9; j++) W2[j] = wg[j];
    }

    const int row0 = blockIdx.x * ROWS_BLK;
    // lane's x base: row0, k = warp*128 + lane*4 (warp's 32 lanes = 512B contig)
    const float* xb = x + (size_t)row0 * K_DIM + warp * 128 + lane * 4;

#define LDROW(t, r) (*reinterpret_cast<const ulonglong2*>( \
        xb + (size_t)((t) * TILE_R + (r)) * K_DIM))

    ulonglong2 c0 = LDROW(0, 0), c1 = LDROW(0, 1),
               c2 = LDROW(0, 2), c3 = LDROW(0, 3);

    float* myred = redw[warp];

    for (int t = 0; t < NT; t++) {
        // prefetch next tile's rows before doing this tile's reduction
        ulonglong2 n0, n1, n2, n3;
        if (t + 1 < NT) {
            n0 = LDROW(t + 1, 0); n1 = LDROW(t + 1, 1);
            n2 = LDROW(t + 1, 2); n3 = LDROW(t + 1, 3);
        }

        // partials: per (row, j): t2 = x(k0,k1)*w(k0,k1) + x(k2,k3)*w(k2,k3)
#define COMPROW(cv, r)                                                     \
        {                                                                  \
            _Pragma("unroll")                                              \
            for (int j = 0; j < 9; j++) {                                  \
                unsigned long long t2 = mul2((cv).x, W2[j].x);             \
                t2 = fma2((cv).y, W2[j].y, t2);                            \
                myred[lane * REDW_STRIDE + (r) * 9 + j] = collapse2(t2);   \
            }                                                              \
        }
        COMPROW(c0, 0) COMPROW(c1, 1) COMPROW(c2, 2) COMPROW(c3, 3)
#undef COMPROW
        __syncwarp();

        // lane reduction: column sums of the 32x36 matrix (conflict-free)
        float o1a = 0.f, o1b = 0.f, o1c = 0.f, o1d = 0.f;
#pragma unroll
        for (int l = 0; l < 32; l += 4) {
            o1a += myred[(l + 0) * REDW_STRIDE + lane];
            o1b += myred[(l + 1) * REDW_STRIDE + lane];
            o1c += myred[(l + 2) * REDW_STRIDE + lane];
            o1d += myred[(l + 3) * REDW_STRIDE + lane];
        }
        float o1 = (o1a + o1b) + (o1c + o1d);

        float o2 = 0.f;
        if (lane < 4) {
#pragma unroll
            for (int l = 0; l < 32; l++)
                o2 += myred[l * REDW_STRIDE + 32 + lane];
        }

        const int p = t & 1;
        redbuf2[p][warp][lane] = o1;
        if (lane < 4) redbuf2[p][warp][32 + lane] = o2;
        __syncthreads();

        // cross-warp: 36 threads each sum 8 warp-partials
        if (tid < 36) {
            float s = 0.f;
#pragma unroll
            for (int w = 0; w < WARPS; w++) s += redbuf2[p][w][tid];
            sumbuf[t * 36 + tid] = s;        // layout [tile][r][9]
        }

        if (t + 1 < NT) { c0 = n0; c1 = n1; c2 = n2; c3 = n3; }
    }
#undef LDROW
    __syncthreads();

    // deferred epilogue: one thread per row (warp 0); W regs dead by now
    if (tid < ROWS_BLK) {
        float a9[9];
#pragma unroll
        for (int j = 0; j < 9; j++) a9[j] = sumbuf[tid * 9 + j];
        row_epilogue(a9, eps, out, row0 + tid, B, n, bmu, bd, bl);
    }
}

// ---------------------------------------------------------------------------
extern "C" void kernel_launch(void* const* d_in, const int* in_sizes, int n_in,
                              void* d_out, int out_size) {
    const float* x   = (const float*)d_in[0];
    const float* eps = (const float*)d_in[1];
    const float* Wmu = (const float*)d_in[2];
    const float* bmu = (const float*)d_in[3];
    const float* Wd  = (const float*)d_in[4];
    const float* bd  = (const float*)d_in[5];
    const float* Wl  = (const float*)d_in[6];
    const float* bl  = (const float*)d_in[7];
    float* out = (float*)d_out;

    const int K = in_sizes[2] / 3;          // 1024
    const int B = in_sizes[0] / K;          // 65536
    const int n = in_sizes[1] / (B * 3);    // 1

    pack_w_kernel<<<(WPACK_ELEMS + 255) / 256, 256>>>(Wmu, Wd, Wl);

    so3_kernel<<<B / ROWS_BLK, THREADS>>>(x, eps, bmu, bd, bl, out, B, n);
}